// round 13
// baseline (speedup 1.0000x reference)
#include <cuda_runtime.h>
#include <math.h>

#define D_     1024
#define BLK    256
#define GRID1  740        // pass1: 5 CTA/SM * 148
#define GRID2  740        // pass2
#define ROWS_  4
#define PAIRS  4
#define NMAX   512
#define MMAX   16384
#define EPS_   1e-5f

typedef unsigned long long ull;
union F4U { float4 f4; ulonglong2 u2; };

// ---- scratch (static device globals; no allocation) ----
__device__ float g_colpart[GRID1 * D_];
__device__ float g_mean[D_];
__device__ float g_gate[MMAX];
__device__ float g_sims[NMAX];
__device__ int   g_valid[NMAX];
__device__ float g_damp, g_qscale;
__device__ int   g_nidx;
__device__ int   g_ctr = 0;    // select arrival counter
__device__ int   g_ctr2 = 0;   // colreduce arrival counter (target 8)

// ---- packed f32x2 helpers ----
__device__ __forceinline__ ull pk2(float lo, float hi) {
    ull r; asm("mov.b64 %0, {%1, %2};" : "=l"(r) : "f"(lo), "f"(hi)); return r;
}
__device__ __forceinline__ float2 upk2(ull v) {
    float2 f; asm("mov.b64 {%0, %1}, %2;" : "=f"(f.x), "=f"(f.y) : "l"(v)); return f;
}
__device__ __forceinline__ ull fma2p(ull a, ull b, ull c) {
    ull r; asm("fma.rn.f32x2 %0, %1, %2, %3;" : "=l"(r) : "l"(a), "l"(b), "l"(c)); return r;
}
__device__ __forceinline__ ull mul2p(ull a, ull b) {
    ull r; asm("mul.rn.f32x2 %0, %1, %2;" : "=l"(r) : "l"(a), "l"(b)); return r;
}
__device__ __forceinline__ float wsum(float v) {
    v += __shfl_xor_sync(0xffffffffu, v, 16);
    v += __shfl_xor_sync(0xffffffffu, v, 8);
    v += __shfl_xor_sync(0xffffffffu, v, 4);
    v += __shfl_xor_sync(0xffffffffu, v, 2);
    v += __shfl_xor_sync(0xffffffffu, v, 1);
    return v;
}
__device__ __forceinline__ float bfly(float a, float b, int lane, int m) {
    float sent = (lane & m) ? a : b;
    float recv = __shfl_xor_sync(0xffffffffu, sent, m);
    return ((lane & m) ? b : a) + recv;
}
__device__ __forceinline__ float tanh_ap(float u) {
    float r; asm("tanh.approx.f32 %0, %1;" : "=f"(r) : "f"(u)); return r;
}
__device__ __forceinline__ ull gelu2p(ull x2) {
    const ull A2   = pk2(0.044715f, 0.044715f);
    const ull ONE2 = pk2(1.0f, 1.0f);
    const ull C2   = pk2(0.7978845608028654f, 0.7978845608028654f);
    const ull H2   = pk2(0.5f, 0.5f);
    ull t2 = mul2p(x2, x2);
    ull p2 = fma2p(t2, A2, ONE2);
    ull u2 = mul2p(mul2p(x2, C2), p2);
    float2 u = upk2(u2);
    ull T2 = pk2(tanh_ap(u.x), tanh_ap(u.y));
    ull hx2 = mul2p(x2, H2);
    return fma2p(T2, hx2, hx2);
}

// ---------------- pass 1: gates + y1 column partial sums ----------------
__global__ void __launch_bounds__(BLK, 5) k_pass1(
    const float* __restrict__ x,
    const float* __restrict__ ema_x, const float* __restrict__ ema_x2,
    const float* __restrict__ ema_y, const float* __restrict__ ema_y2,
    const float* __restrict__ p_lt_in, const float* __restrict__ p_lt_out,
    const float* __restrict__ p_la_in, const float* __restrict__ p_la_out,
    int M)
{
    const int t = threadIdx.x;
    const int c = t * 4;
    const int lane = t & 31, w = t >> 5;

    float4 ex = *(const float4*)(ema_x + c);
    float4 e2 = *(const float4*)(ema_x2 + c);
    float4 ey = *(const float4*)(ema_y + c);
    float4 f2 = *(const float4*)(ema_y2 + c);
    float i0 = 1.0f / (sqrtf(fmaxf(e2.x - ex.x * ex.x, 0.0f)) + EPS_);
    float i1 = 1.0f / (sqrtf(fmaxf(e2.y - ex.y * ex.y, 0.0f)) + EPS_);
    float i2 = 1.0f / (sqrtf(fmaxf(e2.z - ex.z * ex.z, 0.0f)) + EPS_);
    float i3 = 1.0f / (sqrtf(fmaxf(e2.w - ex.w * ex.w, 0.0f)) + EPS_);
    float j0 = 1.0f / (sqrtf(fmaxf(f2.x - ey.x * ey.x, 0.0f)) + EPS_);
    float j1 = 1.0f / (sqrtf(fmaxf(f2.y - ey.y * ey.y, 0.0f)) + EPS_);
    float j2 = 1.0f / (sqrtf(fmaxf(f2.z - ey.z * ey.z, 0.0f)) + EPS_);
    float j3 = 1.0f / (sqrtf(fmaxf(f2.w - ey.w * ey.w, 0.0f)) + EPS_);
    const ull ISX0 = pk2(i0, i1), ISX1 = pk2(i2, i3);
    const ull NX0  = pk2(-ex.x * i0, -ex.y * i1), NX1 = pk2(-ex.z * i2, -ex.w * i3);
    const ull ISY0 = pk2(j0, j1), ISY1 = pk2(j2, j3);
    const ull NY0  = pk2(-ey.x * j0, -ey.y * j1), NY1 = pk2(-ey.z * j2, -ey.w * j3);

    const float tau_in  = expf(p_lt_in[0]);
    const float tau_out = expf(p_lt_out[0]);
    const float a_in    = 1.0f / (1.0f + expf(-p_la_in[0]));
    const float a_out   = 1.0f / (1.0f + expf(-p_la_out[0]));
    const int li = lane & 7;
    const bool isin = (li < 4);
    const float tau_l = isin ? tau_in : tau_out;
    const float a_l   = isin ? a_in : a_out;
    const float b_l   = 1.0f - a_l;

    __shared__ float s_red[2][8][8];

    ull acc0 = 0ull, acc1 = 0ull;
    const int nchunk = M / ROWS_;          // 4096
    int parity = 0;

    for (int ch = blockIdx.x; ch < nchunk; ch += GRID1, parity ^= 1) {
        const float* xp = x + (size_t)ch * (ROWS_ * D_) + c;
        ull ya[ROWS_], yb[ROWS_];
        float zx[ROWS_], zy[ROWS_];
#pragma unroll
        for (int r = 0; r < ROWS_; r++) {
            F4U X; X.f4 = *(const float4*)(xp + r * D_);
            ull xa = X.u2.x, xb = X.u2.y;
            ya[r] = gelu2p(xa);
            yb[r] = gelu2p(xb);
            ull da = fma2p(xa, ISX0, NX0);
            ull db = fma2p(xb, ISX1, NX1);
            ull sx = fma2p(db, db, mul2p(da, da));
            float2 fx = upk2(sx); zx[r] = fx.x + fx.y;
            ull ga_ = fma2p(ya[r], ISY0, NY0);
            ull gb_ = fma2p(yb[r], ISY1, NY1);
            ull sy = fma2p(gb_, gb_, mul2p(ga_, ga_));
            float2 fy = upk2(sy); zy[r] = fy.x + fy.y;
        }

        float v0 = bfly(zx[0], zy[0], lane, 16);
        float v1 = bfly(zx[1], zy[1], lane, 16);
        float v2 = bfly(zx[2], zy[2], lane, 16);
        float v3 = bfly(zx[3], zy[3], lane, 16);
        float u0 = bfly(v0, v2, lane, 8);
        float u1 = bfly(v1, v3, lane, 8);
        float z  = bfly(u0, u1, lane, 4);
        z += __shfl_xor_sync(0xffffffffu, z, 2);
        z += __shfl_xor_sync(0xffffffffu, z, 1);

        if ((lane & 3) == 0) {
            int row = ((lane & 8) >> 2) | ((lane & 4) >> 2);
            int idx = ((lane & 16) >> 2) | row;
            s_red[parity][w][idx] = z;
        }
        __syncthreads();

        float zsum = 0.f;
#pragma unroll
        for (int ww = 0; ww < 8; ww++) zsum += s_red[parity][ww][li];
        zsum *= (1.0f / D_);
        float f = fmaf(a_l, __expf(-tau_l * zsum), b_l);
        float fo = __shfl_sync(0xffffffffu, f, (lane & 3) + 4);
        float g = f * fo;
        if (w == 0 && lane < 4) g_gate[ch * ROWS_ + lane] = g;
#pragma unroll
        for (int r = 0; r < ROWS_; r++) {
            float ga = __shfl_sync(0xffffffffu, g, r);
            ull GA2 = pk2(ga, ga);
            acc0 = fma2p(ya[r], GA2, acc0);
            acc1 = fma2p(yb[r], GA2, acc1);
        }
    }
    F4U A; A.u2.x = acc0; A.u2.y = acc1;
    *(float4*)(g_colpart + blockIdx.x * D_ + c) = A.f4;
}

// ------ fused colreduce (8 coalesced blocks) + sims + select (512x128) --
__global__ void __launch_bounds__(128) k_mid(
    const float* __restrict__ buf, const float* __restrict__ facil,
    const float* __restrict__ p_lkb, const float* __restrict__ p_lkd,
    int N, float invM)
{
    const int n = blockIdx.x;
    const int t = threadIdx.x;
    const int lane = t & 31, w = t >> 5;

    // ---- phase A: blocks 0..7, each thread owns ONE column (coalesced) --
    if (n < 8) {
        const int col = n * 128 + t;
        float s = 0.f;
        const float* cp = g_colpart + col;
#pragma unroll 4
        for (int g = 0; g < GRID1; g++)
            s += cp[(size_t)g * D_];
        g_mean[col] = s * invM;
        __threadfence();
        if (t == 0) atomicAdd(&g_ctr2, 1);
    }
    // ---- wait for all 8 reducer blocks (nanosleep backoff poll) ----
    if (t == 0) {
        while (*(volatile int*)&g_ctr2 < 8) { __nanosleep(200); }
        __threadfence();
    }
    __syncthreads();

    // ---- phase B: sims[n] ----
    const float4* bp = (const float4*)(buf + (size_t)n * D_);
    const float4* mp = (const float4*)g_mean;
    float dot = 0.f, b2 = 0.f, m2 = 0.f;
    int fin = 1;
#pragma unroll
    for (int k = 0; k < 2; k++) {
        float4 bv = bp[t + k * 128];
        float4 mv = mp[t + k * 128];
        dot = fmaf(bv.x, mv.x, fmaf(bv.y, mv.y, fmaf(bv.z, mv.z, fmaf(bv.w, mv.w, dot))));
        b2  = fmaf(bv.x, bv.x, fmaf(bv.y, bv.y, fmaf(bv.z, bv.z, fmaf(bv.w, bv.w, b2))));
        m2  = fmaf(mv.x, mv.x, fmaf(mv.y, mv.y, fmaf(mv.z, mv.z, fmaf(mv.w, mv.w, m2))));
        fin &= (fabsf(bv.x) <= 3.4028234e38f) & (fabsf(bv.y) <= 3.4028234e38f) &
               (fabsf(bv.z) <= 3.4028234e38f) & (fabsf(bv.w) <= 3.4028234e38f);
    }
    dot = wsum(dot); b2 = wsum(b2); m2 = wsum(m2);
    fin = __all_sync(0xffffffffu, fin);
    __shared__ float sd[4], sb[4], sm2[4];
    __shared__ int sf[4];
    if (lane == 0) { sd[w] = dot; sb[w] = b2; sm2[w] = m2; sf[w] = fin; }
    __syncthreads();
    if (t == 0) {
        float dt = sd[0] + sd[1] + sd[2] + sd[3];
        float bb = sb[0] + sb[1] + sb[2] + sb[3];
        float mm = sm2[0] + sm2[1] + sm2[2] + sm2[3];
        float bnorm = fmaxf(sqrtf(bb), 1e-12f);
        float mnorm = fmaxf(sqrtf(mm), 1e-12f);
        g_sims[n] = dt / (bnorm * mnorm);
        g_valid[n] = (sf[0] & sf[1] & sf[2] & sf[3]) && (sqrtf(bb) >= 1e-6f);
    }
    __shared__ int is_last;
    if (t == 0) {
        __threadfence();
        int c = atomicAdd(&g_ctr, 1);
        is_last = (c == gridDim.x - 1) ? 1 : 0;
    }
    __syncthreads();
    if (!is_last) return;

    // ---- phase C: argmax + scalars (last block only) ----
    float best = -3.0e38f; int bidx = 0x7fffffff;
    for (int i = t; i < N; i += 128) {
        float v = g_sims[i];
        if (v > best) { best = v; bidx = i; }
    }
#pragma unroll
    for (int o = 16; o > 0; o >>= 1) {
        float ov = __shfl_xor_sync(0xffffffffu, best, o);
        int   oi = __shfl_xor_sync(0xffffffffu, bidx, o);
        if (ov > best || (ov == best && oi < bidx)) { best = ov; bidx = oi; }
    }
    __shared__ float svv[4]; __shared__ int sii[4];
    if (lane == 0) { svv[w] = best; sii[w] = bidx; }
    __syncthreads();
    if (t == 0) {
        float bv = svv[0]; int bi = sii[0];
#pragma unroll
        for (int i = 1; i < 4; i++) {
            if (svv[i] > bv || (svv[i] == bv && sii[i] < bi)) { bv = svv[i]; bi = sii[i]; }
        }
        float sim_val = fminf(fmaxf(bv, 0.0f), 1.0f);
        float kb = fminf(fmaxf(expf(p_lkb[0]), 0.01f), 4.0f);
        float kd = fminf(fmaxf(expf(p_lkd[0]), 0.01f), 0.9f);
        float fl = facil[bi] * ((sim_val > 0.88f) ? 2.0f : 1.0f);
        float mod = (fl - 1.0f) * sim_val;
        float boost = 1.0f + kb * mod;
        float damp = fmaxf(0.01f, 1.0f - kd * mod);
        g_nidx = bi;
        if (g_valid[bi]) { g_damp = damp; g_qscale = (boost - damp) / damp; }
        else             { g_damp = 1.0f; g_qscale = 0.0f; }
        g_ctr = 0;
        g_ctr2 = 0;   // reset both for next graph replay
    }
}

// ---------------- pass 2: warp-pair per row (R7 scalar version) ---------
__global__ void __launch_bounds__(BLK, 5) k_pass2(
    const float* __restrict__ x, const float* __restrict__ buf,
    float* __restrict__ out, int M)
{
    __shared__ float4 s_v[D_ / 4];
    __shared__ float s_p[2][PAIRS][2];
    const int t = threadIdx.x;
    const int lane = t & 31, w = t >> 5;
    const int pair = w >> 1, half = w & 1;
    const float damp = g_damp;
    const float qscale = g_qscale;
    const int ni = g_nidx;

    {
        const float4* vp = (const float4*)(buf + (size_t)ni * D_);
        for (int i = t; i < D_ / 4; i += BLK) s_v[i] = vp[i];
    }
    __syncthreads();

    const int voff = half * 128 + lane;
    int parity = 0;
    for (int row = blockIdx.x * PAIRS + pair; row < M;
         row += GRID2 * PAIRS, parity ^= 1) {
        const float4* xp = (const float4*)(x + (size_t)row * D_) + voff;
        const float gad = 0.5f * damp * g_gate[row];
        float4 Y[4];
        float proj = 0.f;
#pragma unroll
        for (int k = 0; k < 4; k++) {
            float4 X = __ldcs(xp + 32 * k);
            float4 V = s_v[voff + 32 * k];
            float4 yy;
            float u0 = 0.7978845608028654f * fmaf(0.044715f * X.x, X.x * X.x, X.x);
            float u1 = 0.7978845608028654f * fmaf(0.044715f * X.y, X.y * X.y, X.y);
            float u2 = 0.7978845608028654f * fmaf(0.044715f * X.z, X.z * X.z, X.z);
            float u3 = 0.7978845608028654f * fmaf(0.044715f * X.w, X.w * X.w, X.w);
            yy.x = (X.x * gad) * (1.0f + tanh_ap(u0));
            yy.y = (X.y * gad) * (1.0f + tanh_ap(u1));
            yy.z = (X.z * gad) * (1.0f + tanh_ap(u2));
            yy.w = (X.w * gad) * (1.0f + tanh_ap(u3));
            Y[k] = yy;
            proj = fmaf(yy.x, V.x, fmaf(yy.y, V.y, fmaf(yy.z, V.z, fmaf(yy.w, V.w, proj))));
        }
        proj = wsum(proj);
        if (lane == 0) s_p[parity][pair][half] = proj;
        asm volatile("bar.sync %0, %1;" :: "r"(pair + 1), "r"(64) : "memory");
        const float q = (s_p[parity][pair][0] + s_p[parity][pair][1]) * qscale;
        float4* op = (float4*)(out + (size_t)row * D_) + voff;
#pragma unroll
        for (int k = 0; k < 4; k++) {
            float4 V = s_v[voff + 32 * k];
            float4 O;
            O.x = fmaf(q, V.x, Y[k].x);
            O.y = fmaf(q, V.y, Y[k].y);
            O.z = fmaf(q, V.z, Y[k].z);
            O.w = fmaf(q, V.w, Y[k].w);
            __stcs(op + 32 * k, O);
        }
    }
}

extern "C" void kernel_launch(void* const* d_in, const int* in_sizes, int n_in,
                              void* d_out, int out_size)
{
    const float* x      = (const float*)d_in[0];
    const float* lt_in  = (const float*)d_in[1];
    const float* lt_out = (const float*)d_in[2];
    const float* la_in  = (const float*)d_in[3];
    const float* la_out = (const float*)d_in[4];
    const float* lkb    = (const float*)d_in[5];
    const float* lkd    = (const float*)d_in[6];
    const float* ema_x  = (const float*)d_in[7];
    const float* ema_x2 = (const float*)d_in[8];
    const float* ema_y  = (const float*)d_in[9];
    const float* ema_y2 = (const float*)d_in[10];
    const float* buf    = (const float*)d_in[11];
    const float* facil  = (const float*)d_in[12];

    const int M = in_sizes[0] / D_;   // 16384
    const int N = in_sizes[11] / D_;  // 512
    float* out = (float*)d_out;

    k_pass1<<<GRID1, BLK>>>(x, ema_x, ema_x2, ema_y, ema_y2,
                            lt_in, lt_out, la_in, la_out, M);
    k_mid<<<N, 128>>>(buf, facil, lkb, lkd, N, 1.0f / (float)M);
    k_pass2<<<GRID2, BLK>>>(x, buf, out, M);
}

// round 14
// speedup vs baseline: 1.9717x; 1.9717x over previous
#include <cuda_runtime.h>
#include <math.h>

#define D_     1024
#define BLK    256
#define GRID1  512        // pass1: 4096 chunks / 512 = 8 iters exact
#define GRID2  740        // pass2: 5 CTA/SM * 148
#define ROWS_  4
#define PAIRS  4
#define NMAX   512
#define MMAX   16384
#define EPS_   1e-5f

typedef unsigned long long ull;
union F4U { float4 f4; ulonglong2 u2; };

// ---- scratch (static device globals; no allocation) ----
__device__ float g_colpart[GRID1 * D_];
__device__ float g_mean[D_];
__device__ float g_gate[MMAX];
__device__ float g_sims[NMAX];
__device__ int   g_valid[NMAX];
__device__ float g_damp, g_qscale;
__device__ int   g_nidx;
__device__ int   g_ctr = 0;    // select arrival counter
__device__ int   g_ctr2 = 0;   // colreduce arrival counter (target 128)

// ---- packed f32x2 helpers ----
__device__ __forceinline__ ull pk2(float lo, float hi) {
    ull r; asm("mov.b64 %0, {%1, %2};" : "=l"(r) : "f"(lo), "f"(hi)); return r;
}
__device__ __forceinline__ float2 upk2(ull v) {
    float2 f; asm("mov.b64 {%0, %1}, %2;" : "=f"(f.x), "=f"(f.y) : "l"(v)); return f;
}
__device__ __forceinline__ ull fma2p(ull a, ull b, ull c) {
    ull r; asm("fma.rn.f32x2 %0, %1, %2, %3;" : "=l"(r) : "l"(a), "l"(b), "l"(c)); return r;
}
__device__ __forceinline__ ull mul2p(ull a, ull b) {
    ull r; asm("mul.rn.f32x2 %0, %1, %2;" : "=l"(r) : "l"(a), "l"(b)); return r;
}
__device__ __forceinline__ float wsum(float v) {
    v += __shfl_xor_sync(0xffffffffu, v, 16);
    v += __shfl_xor_sync(0xffffffffu, v, 8);
    v += __shfl_xor_sync(0xffffffffu, v, 4);
    v += __shfl_xor_sync(0xffffffffu, v, 2);
    v += __shfl_xor_sync(0xffffffffu, v, 1);
    return v;
}
__device__ __forceinline__ float bfly(float a, float b, int lane, int m) {
    float sent = (lane & m) ? a : b;
    float recv = __shfl_xor_sync(0xffffffffu, sent, m);
    return ((lane & m) ? b : a) + recv;
}
__device__ __forceinline__ float tanh_ap(float u) {
    float r; asm("tanh.approx.f32 %0, %1;" : "=f"(r) : "f"(u)); return r;
}
__device__ __forceinline__ void pf_l2(const void* p) {
    asm volatile("prefetch.global.L2 [%0];" :: "l"(p));
}
__device__ __forceinline__ ull gelu2p(ull x2) {
    const ull A2   = pk2(0.044715f, 0.044715f);
    const ull ONE2 = pk2(1.0f, 1.0f);
    const ull C2   = pk2(0.7978845608028654f, 0.7978845608028654f);
    const ull H2   = pk2(0.5f, 0.5f);
    ull t2 = mul2p(x2, x2);
    ull p2 = fma2p(t2, A2, ONE2);
    ull u2 = mul2p(mul2p(x2, C2), p2);
    float2 u = upk2(u2);
    ull T2 = pk2(tanh_ap(u.x), tanh_ap(u.y));
    ull hx2 = mul2p(x2, H2);
    return fma2p(T2, hx2, hx2);
}

// ---------------- pass 1: gates + y1 column partial sums ----------------
__global__ void __launch_bounds__(BLK, 5) k_pass1(
    const float* __restrict__ x,
    const float* __restrict__ ema_x, const float* __restrict__ ema_x2,
    const float* __restrict__ ema_y, const float* __restrict__ ema_y2,
    const float* __restrict__ p_lt_in, const float* __restrict__ p_lt_out,
    const float* __restrict__ p_la_in, const float* __restrict__ p_la_out,
    int M)
{
    const int t = threadIdx.x;
    const int c = t * 4;
    const int lane = t & 31, w = t >> 5;

    float4 ex = *(const float4*)(ema_x + c);
    float4 e2 = *(const float4*)(ema_x2 + c);
    float4 ey = *(const float4*)(ema_y + c);
    float4 f2 = *(const float4*)(ema_y2 + c);
    float i0 = 1.0f / (sqrtf(fmaxf(e2.x - ex.x * ex.x, 0.0f)) + EPS_);
    float i1 = 1.0f / (sqrtf(fmaxf(e2.y - ex.y * ex.y, 0.0f)) + EPS_);
    float i2 = 1.0f / (sqrtf(fmaxf(e2.z - ex.z * ex.z, 0.0f)) + EPS_);
    float i3 = 1.0f / (sqrtf(fmaxf(e2.w - ex.w * ex.w, 0.0f)) + EPS_);
    float j0 = 1.0f / (sqrtf(fmaxf(f2.x - ey.x * ey.x, 0.0f)) + EPS_);
    float j1 = 1.0f / (sqrtf(fmaxf(f2.y - ey.y * ey.y, 0.0f)) + EPS_);
    float j2 = 1.0f / (sqrtf(fmaxf(f2.z - ey.z * ey.z, 0.0f)) + EPS_);
    float j3 = 1.0f / (sqrtf(fmaxf(f2.w - ey.w * ey.w, 0.0f)) + EPS_);
    const ull ISX0 = pk2(i0, i1), ISX1 = pk2(i2, i3);
    const ull NX0  = pk2(-ex.x * i0, -ex.y * i1), NX1 = pk2(-ex.z * i2, -ex.w * i3);
    const ull ISY0 = pk2(j0, j1), ISY1 = pk2(j2, j3);
    const ull NY0  = pk2(-ey.x * j0, -ey.y * j1), NY1 = pk2(-ey.z * j2, -ey.w * j3);

    const float tau_in  = expf(p_lt_in[0]);
    const float tau_out = expf(p_lt_out[0]);
    const float a_in    = 1.0f / (1.0f + expf(-p_la_in[0]));
    const float a_out   = 1.0f / (1.0f + expf(-p_la_out[0]));
    const int li = lane & 7;
    const bool isin = (li < 4);
    const float tau_l = isin ? tau_in : tau_out;
    const float a_l   = isin ? a_in : a_out;
    const float b_l   = 1.0f - a_l;

    __shared__ float s_red[2][8][8];

    ull acc0 = 0ull, acc1 = 0ull;
    const int nchunk = M / ROWS_;          // 4096
    int parity = 0;

    for (int ch = blockIdx.x; ch < nchunk; ch += GRID1, parity ^= 1) {
        // L2 prefetch of NEXT chunk (one prefetch per 128B line)
        int chn = ch + GRID1;
        if (chn < nchunk && (t & 7) == 0) {
            const char* pp = (const char*)(x + (size_t)chn * (ROWS_ * D_)) + c * 4;
#pragma unroll
            for (int r = 0; r < ROWS_; r++) pf_l2(pp + r * (D_ * 4));
        }

        const float* xp = x + (size_t)ch * (ROWS_ * D_) + c;
        ull ya[ROWS_], yb[ROWS_];
        float zx[ROWS_], zy[ROWS_];
#pragma unroll
        for (int r = 0; r < ROWS_; r++) {
            F4U X; X.f4 = *(const float4*)(xp + r * D_);
            ull xa = X.u2.x, xb = X.u2.y;
            ya[r] = gelu2p(xa);
            yb[r] = gelu2p(xb);
            ull da = fma2p(xa, ISX0, NX0);
            ull db = fma2p(xb, ISX1, NX1);
            ull sx = fma2p(db, db, mul2p(da, da));
            float2 fx = upk2(sx); zx[r] = fx.x + fx.y;
            ull ga_ = fma2p(ya[r], ISY0, NY0);
            ull gb_ = fma2p(yb[r], ISY1, NY1);
            ull sy = fma2p(gb_, gb_, mul2p(ga_, ga_));
            float2 fy = upk2(sy); zy[r] = fy.x + fy.y;
        }

        float v0 = bfly(zx[0], zy[0], lane, 16);
        float v1 = bfly(zx[1], zy[1], lane, 16);
        float v2 = bfly(zx[2], zy[2], lane, 16);
        float v3 = bfly(zx[3], zy[3], lane, 16);
        float u0 = bfly(v0, v2, lane, 8);
        float u1 = bfly(v1, v3, lane, 8);
        float z  = bfly(u0, u1, lane, 4);
        z += __shfl_xor_sync(0xffffffffu, z, 2);
        z += __shfl_xor_sync(0xffffffffu, z, 1);

        if ((lane & 3) == 0) {
            int row = ((lane & 8) >> 2) | ((lane & 4) >> 2);
            int idx = ((lane & 16) >> 2) | row;
            s_red[parity][w][idx] = z;
        }
        __syncthreads();

        float zsum = 0.f;
#pragma unroll
        for (int ww = 0; ww < 8; ww++) zsum += s_red[parity][ww][li];
        zsum *= (1.0f / D_);
        float f = fmaf(a_l, __expf(-tau_l * zsum), b_l);
        float fo = __shfl_sync(0xffffffffu, f, (lane & 3) + 4);
        float g = f * fo;
        if (w == 0 && lane < 4) g_gate[ch * ROWS_ + lane] = g;
#pragma unroll
        for (int r = 0; r < ROWS_; r++) {
            float ga = __shfl_sync(0xffffffffu, g, r);
            ull GA2 = pk2(ga, ga);
            acc0 = fma2p(ya[r], GA2, acc0);
            acc1 = fma2p(yb[r], GA2, acc1);
        }
    }
    F4U A; A.u2.x = acc0; A.u2.y = acc1;
    *(float4*)(g_colpart + blockIdx.x * D_ + c) = A.f4;
}

// ------ fused colreduce (R7 layout: 128 blocks x 32 slices) + sims ------
__global__ void __launch_bounds__(128) k_mid(
    const float* __restrict__ buf, const float* __restrict__ facil,
    const float* __restrict__ p_lkb, const float* __restrict__ p_lkd,
    int N, float invM)
{
    const int n = blockIdx.x;
    const int t = threadIdx.x;
    const int lane = t & 31, w = t >> 5;

    // ---- phase A: blocks 0..127 reduce 8 columns each (32 slices) ----
    if (n < 128) {
        const int col = n * 8 + (t & 7);
        const int gs = t >> 3;                 // 0..15
        float s = 0.f;
#pragma unroll
        for (int k = 0; k < GRID1 / 16; k++)   // 32 slices per thread
            s += g_colpart[(gs + k * 16) * D_ + col];
        __shared__ float sm[16][8];
        sm[gs][t & 7] = s;
        __syncthreads();
        if (t < 8) {
            float tot = 0.f;
#pragma unroll
            for (int i = 0; i < 16; i++) tot += sm[i][t];
            g_mean[n * 8 + t] = tot * invM;
        }
        if (t == 0) { __threadfence(); atomicAdd(&g_ctr2, 1); }
    }
    // ---- wait for all means ----
    if (t == 0) {
        while (atomicAdd(&g_ctr2, 0) < 128) { }
    }
    __syncthreads();

    // ---- phase B: sims[n] ----
    const float4* bp = (const float4*)(buf + (size_t)n * D_);
    const float4* mp = (const float4*)g_mean;
    float dot = 0.f, b2 = 0.f, m2 = 0.f;
    int fin = 1;
#pragma unroll
    for (int k = 0; k < 2; k++) {
        float4 bv = bp[t + k * 128];
        float4 mv = mp[t + k * 128];
        dot = fmaf(bv.x, mv.x, fmaf(bv.y, mv.y, fmaf(bv.z, mv.z, fmaf(bv.w, mv.w, dot))));
        b2  = fmaf(bv.x, bv.x, fmaf(bv.y, bv.y, fmaf(bv.z, bv.z, fmaf(bv.w, bv.w, b2))));
        m2  = fmaf(mv.x, mv.x, fmaf(mv.y, mv.y, fmaf(mv.z, mv.z, fmaf(mv.w, mv.w, m2))));
        fin &= (fabsf(bv.x) <= 3.4028234e38f) & (fabsf(bv.y) <= 3.4028234e38f) &
               (fabsf(bv.z) <= 3.4028234e38f) & (fabsf(bv.w) <= 3.4028234e38f);
    }
    dot = wsum(dot); b2 = wsum(b2); m2 = wsum(m2);
    fin = __all_sync(0xffffffffu, fin);
    __shared__ float sd[4], sb[4], sm2[4];
    __shared__ int sf[4];
    if (lane == 0) { sd[w] = dot; sb[w] = b2; sm2[w] = m2; sf[w] = fin; }
    __syncthreads();
    if (t == 0) {
        float dt = sd[0] + sd[1] + sd[2] + sd[3];
        float bb = sb[0] + sb[1] + sb[2] + sb[3];
        float mm = sm2[0] + sm2[1] + sm2[2] + sm2[3];
        float bnorm = fmaxf(sqrtf(bb), 1e-12f);
        float mnorm = fmaxf(sqrtf(mm), 1e-12f);
        g_sims[n] = dt / (bnorm * mnorm);
        g_valid[n] = (sf[0] & sf[1] & sf[2] & sf[3]) && (sqrtf(bb) >= 1e-6f);
    }
    __shared__ int is_last;
    if (t == 0) {
        __threadfence();
        int c = atomicAdd(&g_ctr, 1);
        is_last = (c == gridDim.x - 1) ? 1 : 0;
    }
    __syncthreads();
    if (!is_last) return;

    // ---- phase C: argmax + scalars ----
    float best = -3.0e38f; int bidx = 0x7fffffff;
    for (int i = t; i < N; i += 128) {
        float v = g_sims[i];
        if (v > best) { best = v; bidx = i; }
    }
#pragma unroll
    for (int o = 16; o > 0; o >>= 1) {
        float ov = __shfl_xor_sync(0xffffffffu, best, o);
        int   oi = __shfl_xor_sync(0xffffffffu, bidx, o);
        if (ov > best || (ov == best && oi < bidx)) { best = ov; bidx = oi; }
    }
    __shared__ float svv[4]; __shared__ int sii[4];
    if (lane == 0) { svv[w] = best; sii[w] = bidx; }
    __syncthreads();
    if (t == 0) {
        float bv = svv[0]; int bi = sii[0];
#pragma unroll
        for (int i = 1; i < 4; i++) {
            if (svv[i] > bv || (svv[i] == bv && sii[i] < bi)) { bv = svv[i]; bi = sii[i]; }
        }
        float sim_val = fminf(fmaxf(bv, 0.0f), 1.0f);
        float kb = fminf(fmaxf(expf(p_lkb[0]), 0.01f), 4.0f);
        float kd = fminf(fmaxf(expf(p_lkd[0]), 0.01f), 0.9f);
        float fl = facil[bi] * ((sim_val > 0.88f) ? 2.0f : 1.0f);
        float mod = (fl - 1.0f) * sim_val;
        float boost = 1.0f + kb * mod;
        float damp = fmaxf(0.01f, 1.0f - kd * mod);
        g_nidx = bi;
        if (g_valid[bi]) { g_damp = damp; g_qscale = (boost - damp) / damp; }
        else             { g_damp = 1.0f; g_qscale = 0.0f; }
        g_ctr = 0;
        g_ctr2 = 0;   // reset both for next graph replay
    }
}

// ---------------- pass 2: warp-pair per row + L2 prefetch ---------------
__global__ void __launch_bounds__(BLK, 5) k_pass2(
    const float* __restrict__ x, const float* __restrict__ buf,
    float* __restrict__ out, int M)
{
    __shared__ float4 s_v[D_ / 4];
    __shared__ float s_p[2][PAIRS][2];
    const int t = threadIdx.x;
    const int lane = t & 31, w = t >> 5;
    const int pair = w >> 1, half = w & 1;
    const float damp = g_damp;
    const float qscale = g_qscale;
    const int ni = g_nidx;

    {
        const float4* vp = (const float4*)(buf + (size_t)ni * D_);
        for (int i = t; i < D_ / 4; i += BLK) s_v[i] = vp[i];
    }
    __syncthreads();

    const int voff = half * 128 + lane;
    int parity = 0;
    for (int row = blockIdx.x * PAIRS + pair; row < M;
         row += GRID2 * PAIRS, parity ^= 1) {
        // L2 prefetch of NEXT row's half (one prefetch per 128B line)
        int rown = row + GRID2 * PAIRS;
        if (rown < M && (lane & 7) == 0) {
            const char* pp = (const char*)((const float4*)(x + (size_t)rown * D_) + voff);
#pragma unroll
            for (int k = 0; k < 4; k++) pf_l2(pp + k * 512);
        }

        const float4* xp = (const float4*)(x + (size_t)row * D_) + voff;
        const float gad = 0.5f * damp * g_gate[row];
        float4 Y[4];
        float proj = 0.f;
#pragma unroll
        for (int k = 0; k < 4; k++) {
            float4 X = __ldcs(xp + 32 * k);
            float4 V = s_v[voff + 32 * k];
            float4 yy;
            float u0 = 0.7978845608028654f * fmaf(0.044715f * X.x, X.x * X.x, X.x);
            float u1 = 0.7978845608028654f * fmaf(0.044715f * X.y, X.y * X.y, X.y);
            float u2 = 0.7978845608028654f * fmaf(0.044715f * X.z, X.z * X.z, X.z);
            float u3 = 0.7978845608028654f * fmaf(0.044715f * X.w, X.w * X.w, X.w);
            yy.x = (X.x * gad) * (1.0f + tanh_ap(u0));
            yy.y = (X.y * gad) * (1.0f + tanh_ap(u1));
            yy.z = (X.z * gad) * (1.0f + tanh_ap(u2));
            yy.w = (X.w * gad) * (1.0f + tanh_ap(u3));
            Y[k] = yy;
            proj = fmaf(yy.x, V.x, fmaf(yy.y, V.y, fmaf(yy.z, V.z, fmaf(yy.w, V.w, proj))));
        }
        proj = wsum(proj);
        if (lane == 0) s_p[parity][pair][half] = proj;
        asm volatile("bar.sync %0, %1;" :: "r"(pair + 1), "r"(64) : "memory");
        const float q = (s_p[parity][pair][0] + s_p[parity][pair][1]) * qscale;
        float4* op = (float4*)(out + (size_t)row * D_) + voff;
#pragma unroll
        for (int k = 0; k < 4; k++) {
            float4 V = s_v[voff + 32 * k];
            float4 O;
            O.x = fmaf(q, V.x, Y[k].x);
            O.y = fmaf(q, V.y, Y[k].y);
            O.z = fmaf(q, V.z, Y[k].z);
            O.w = fmaf(q, V.w, Y[k].w);
            __stcs(op + 32 * k, O);
        }
    }
}

extern "C" void kernel_launch(void* const* d_in, const int* in_sizes, int n_in,
                              void* d_out, int out_size)
{
    const float* x      = (const float*)d_in[0];
    const float* lt_in  = (const float*)d_in[1];
    const float* lt_out = (const float*)d_in[2];
    const float* la_in  = (const float*)d_in[3];
    const float* la_out = (const float*)d_in[4];
    const float* lkb    = (const float*)d_in[5];
    const float* lkd    = (const float*)d_in[6];
    const float* ema_x  = (const float*)d_in[7];
    const float* ema_x2 = (const float*)d_in[8];
    const float* ema_y  = (const float*)d_in[9];
    const float* ema_y2 = (const float*)d_in[10];
    const float* buf    = (const float*)d_in[11];
    const float* facil  = (const float*)d_in[12];

    const int M = in_sizes[0] / D_;   // 16384
    const int N = in_sizes[11] / D_;  // 512
    float* out = (float*)d_out;

    k_pass1<<<GRID1, BLK>>>(x, ema_x, ema_x2, ema_y, ema_y2,
                            lt_in, lt_out, la_in, la_out, M);
    k_mid<<<N, 128>>>(buf, facil, lkb, lkd, N, 1.0f / (float)M);
    k_pass2<<<GRID2, BLK>>>(x, buf, out, M);
}

// round 15
// speedup vs baseline: 2.1797x; 1.1055x over previous
#include <cuda_runtime.h>
#include <math.h>

#define D_     1024
#define BLK    256
#define GRID1  512        // pass1: 4096 chunks / 512 = 8 iters exact
#define GRID2  512        // pass2: 4096 row-groups / 512 = 8 iters exact
#define ROWS_  4
#define PAIRS  4
#define NMAX   512
#define MMAX   16384
#define EPS_   1e-5f

typedef unsigned long long ull;
union F4U { float4 f4; ulonglong2 u2; };

// ---- scratch (static device globals; no allocation) ----
__device__ float g_colpart[GRID1 * D_];
__device__ float g_mean[D_];
__device__ float g_gate[MMAX];
__device__ float g_sims[NMAX];
__device__ int   g_valid[NMAX];
__device__ float g_damp, g_qscale;
__device__ int   g_nidx;
__device__ int   g_ctr = 0;
__device__ int   g_ctr2 = 0;

// ---- packed f32x2 helpers ----
__device__ __forceinline__ ull pk2(float lo, float hi) {
    ull r; asm("mov.b64 %0, {%1, %2};" : "=l"(r) : "f"(lo), "f"(hi)); return r;
}
__device__ __forceinline__ float2 upk2(ull v) {
    float2 f; asm("mov.b64 {%0, %1}, %2;" : "=f"(f.x), "=f"(f.y) : "l"(v)); return f;
}
__device__ __forceinline__ ull fma2p(ull a, ull b, ull c) {
    ull r; asm("fma.rn.f32x2 %0, %1, %2, %3;" : "=l"(r) : "l"(a), "l"(b), "l"(c)); return r;
}
__device__ __forceinline__ ull mul2p(ull a, ull b) {
    ull r; asm("mul.rn.f32x2 %0, %1, %2;" : "=l"(r) : "l"(a), "l"(b)); return r;
}
__device__ __forceinline__ float wsum(float v) {
    v += __shfl_xor_sync(0xffffffffu, v, 16);
    v += __shfl_xor_sync(0xffffffffu, v, 8);
    v += __shfl_xor_sync(0xffffffffu, v, 4);
    v += __shfl_xor_sync(0xffffffffu, v, 2);
    v += __shfl_xor_sync(0xffffffffu, v, 1);
    return v;
}
__device__ __forceinline__ float bfly(float a, float b, int lane, int m) {
    float sent = (lane & m) ? a : b;
    float recv = __shfl_xor_sync(0xffffffffu, sent, m);
    return ((lane & m) ? b : a) + recv;
}
__device__ __forceinline__ float tanh_ap(float u) {
    float r; asm("tanh.approx.f32 %0, %1;" : "=f"(r) : "f"(u)); return r;
}
__device__ __forceinline__ ull gelu2p(ull x2) {
    const ull A2   = pk2(0.044715f, 0.044715f);
    const ull ONE2 = pk2(1.0f, 1.0f);
    const ull C2   = pk2(0.7978845608028654f, 0.7978845608028654f);
    const ull H2   = pk2(0.5f, 0.5f);
    ull t2 = mul2p(x2, x2);
    ull p2 = fma2p(t2, A2, ONE2);
    ull u2 = mul2p(mul2p(x2, C2), p2);
    float2 u = upk2(u2);
    ull T2 = pk2(tanh_ap(u.x), tanh_ap(u.y));
    ull hx2 = mul2p(x2, H2);
    return fma2p(T2, hx2, hx2);
}

// ------- pass 1: gates + colpart, register-pipelined x loads ------------
__global__ void __launch_bounds__(BLK, 4) k_pass1(
    const float* __restrict__ x,
    const float* __restrict__ ema_x, const float* __restrict__ ema_x2,
    const float* __restrict__ ema_y, const float* __restrict__ ema_y2,
    const float* __restrict__ p_lt_in, const float* __restrict__ p_lt_out,
    const float* __restrict__ p_la_in, const float* __restrict__ p_la_out,
    int M)
{
    const int t = threadIdx.x;
    const int c = t * 4;
    const int lane = t & 31, w = t >> 5;

    float4 ex = *(const float4*)(ema_x + c);
    float4 e2 = *(const float4*)(ema_x2 + c);
    float4 ey = *(const float4*)(ema_y + c);
    float4 f2 = *(const float4*)(ema_y2 + c);
    float i0 = 1.0f / (sqrtf(fmaxf(e2.x - ex.x * ex.x, 0.0f)) + EPS_);
    float i1 = 1.0f / (sqrtf(fmaxf(e2.y - ex.y * ex.y, 0.0f)) + EPS_);
    float i2 = 1.0f / (sqrtf(fmaxf(e2.z - ex.z * ex.z, 0.0f)) + EPS_);
    float i3 = 1.0f / (sqrtf(fmaxf(e2.w - ex.w * ex.w, 0.0f)) + EPS_);
    float j0 = 1.0f / (sqrtf(fmaxf(f2.x - ey.x * ey.x, 0.0f)) + EPS_);
    float j1 = 1.0f / (sqrtf(fmaxf(f2.y - ey.y * ey.y, 0.0f)) + EPS_);
    float j2 = 1.0f / (sqrtf(fmaxf(f2.z - ey.z * ey.z, 0.0f)) + EPS_);
    float j3 = 1.0f / (sqrtf(fmaxf(f2.w - ey.w * ey.w, 0.0f)) + EPS_);
    const ull ISX0 = pk2(i0, i1), ISX1 = pk2(i2, i3);
    const ull NX0  = pk2(-ex.x * i0, -ex.y * i1), NX1 = pk2(-ex.z * i2, -ex.w * i3);
    const ull ISY0 = pk2(j0, j1), ISY1 = pk2(j2, j3);
    const ull NY0  = pk2(-ey.x * j0, -ey.y * j1), NY1 = pk2(-ey.z * j2, -ey.w * j3);

    const float tau_in  = expf(p_lt_in[0]);
    const float tau_out = expf(p_lt_out[0]);
    const float a_in    = 1.0f / (1.0f + expf(-p_la_in[0]));
    const float a_out   = 1.0f / (1.0f + expf(-p_la_out[0]));
    const int li = lane & 7;
    const bool isin = (li < 4);
    const float tau_l = isin ? tau_in : tau_out;
    const float a_l   = isin ? a_in : a_out;
    const float b_l   = 1.0f - a_l;

    __shared__ float s_red[2][8][8];

    ull acc0 = 0ull, acc1 = 0ull;
    const int nchunk = M / ROWS_;          // 4096

    // prologue: load first chunk
    int ch = blockIdx.x;
    ull xa[ROWS_], xb[ROWS_];
    {
        const float* xp = x + (size_t)ch * (ROWS_ * D_) + c;
#pragma unroll
        for (int r = 0; r < ROWS_; r++) {
            F4U X; X.f4 = *(const float4*)(xp + r * D_);
            xa[r] = X.u2.x; xb[r] = X.u2.y;
        }
    }
    int parity = 0;

    while (ch < nchunk) {
        // issue NEXT chunk's loads now; consumed next iteration
        const int chn = ch + GRID1;
        ull na[ROWS_], nb[ROWS_];
        if (chn < nchunk) {
            const float* xq = x + (size_t)chn * (ROWS_ * D_) + c;
#pragma unroll
            for (int r = 0; r < ROWS_; r++) {
                F4U X; X.f4 = *(const float4*)(xq + r * D_);
                na[r] = X.u2.x; nb[r] = X.u2.y;
            }
        }

        ull ya[ROWS_], yb[ROWS_];
        float zx[ROWS_], zy[ROWS_];
#pragma unroll
        for (int r = 0; r < ROWS_; r++) {
            ya[r] = gelu2p(xa[r]);
            yb[r] = gelu2p(xb[r]);
            ull da = fma2p(xa[r], ISX0, NX0);
            ull db = fma2p(xb[r], ISX1, NX1);
            ull sx = fma2p(db, db, mul2p(da, da));
            float2 fx = upk2(sx); zx[r] = fx.x + fx.y;
            ull ga_ = fma2p(ya[r], ISY0, NY0);
            ull gb_ = fma2p(yb[r], ISY1, NY1);
            ull sy = fma2p(gb_, gb_, mul2p(ga_, ga_));
            float2 fy = upk2(sy); zy[r] = fy.x + fy.y;
        }

        float v0 = bfly(zx[0], zy[0], lane, 16);
        float v1 = bfly(zx[1], zy[1], lane, 16);
        float v2 = bfly(zx[2], zy[2], lane, 16);
        float v3 = bfly(zx[3], zy[3], lane, 16);
        float u0 = bfly(v0, v2, lane, 8);
        float u1 = bfly(v1, v3, lane, 8);
        float z  = bfly(u0, u1, lane, 4);
        z += __shfl_xor_sync(0xffffffffu, z, 2);
        z += __shfl_xor_sync(0xffffffffu, z, 1);

        if ((lane & 3) == 0) {
            int row = ((lane & 8) >> 2) | ((lane & 4) >> 2);
            int idx = ((lane & 16) >> 2) | row;
            s_red[parity][w][idx] = z;
        }
        __syncthreads();

        float zsum = 0.f;
#pragma unroll
        for (int ww = 0; ww < 8; ww++) zsum += s_red[parity][ww][li];
        zsum *= (1.0f / D_);
        float f = fmaf(a_l, __expf(-tau_l * zsum), b_l);
        float fo = __shfl_sync(0xffffffffu, f, (lane & 3) + 4);
        float g = f * fo;
        if (w == 0 && lane < 4) g_gate[ch * ROWS_ + lane] = g;
#pragma unroll
        for (int r = 0; r < ROWS_; r++) {
            float ga = __shfl_sync(0xffffffffu, g, r);
            ull GA2 = pk2(ga, ga);
            acc0 = fma2p(ya[r], GA2, acc0);
            acc1 = fma2p(yb[r], GA2, acc1);
        }

        // rotate pipeline
        ch = chn;
        parity ^= 1;
#pragma unroll
        for (int r = 0; r < ROWS_; r++) { xa[r] = na[r]; xb[r] = nb[r]; }
    }
    F4U A; A.u2.x = acc0; A.u2.y = acc1;
    *(float4*)(g_colpart + blockIdx.x * D_ + c) = A.f4;
}

// ------ fused colreduce (128 blocks x 32 slices) + sims + select --------
__global__ void __launch_bounds__(128) k_mid(
    const float* __restrict__ buf, const float* __restrict__ facil,
    const float* __restrict__ p_lkb, const float* __restrict__ p_lkd,
    int N, float invM)
{
    const int n = blockIdx.x;
    const int t = threadIdx.x;
    const int lane = t & 31, w = t >> 5;

    if (n < 128) {
        const int col = n * 8 + (t & 7);
        const int gs = t >> 3;                 // 0..15
        float s = 0.f;
#pragma unroll
        for (int k = 0; k < GRID1 / 16; k++)   // 32 slices per thread
            s += g_colpart[(gs + k * 16) * D_ + col];
        __shared__ float sm[16][8];
        sm[gs][t & 7] = s;
        __syncthreads();
        if (t < 8) {
            float tot = 0.f;
#pragma unroll
            for (int i = 0; i < 16; i++) tot += sm[i][t];
            g_mean[n * 8 + t] = tot * invM;
        }
        if (t == 0) { __threadfence(); atomicAdd(&g_ctr2, 1); }
    }
    if (t == 0) {
        while (atomicAdd(&g_ctr2, 0) < 128) { }
    }
    __syncthreads();

    const float4* bp = (const float4*)(buf + (size_t)n * D_);
    const float4* mp = (const float4*)g_mean;
    float dot = 0.f, b2 = 0.f, m2 = 0.f;
    int fin = 1;
#pragma unroll
    for (int k = 0; k < 2; k++) {
        float4 bv = bp[t + k * 128];
        float4 mv = mp[t + k * 128];
        dot = fmaf(bv.x, mv.x, fmaf(bv.y, mv.y, fmaf(bv.z, mv.z, fmaf(bv.w, mv.w, dot))));
        b2  = fmaf(bv.x, bv.x, fmaf(bv.y, bv.y, fmaf(bv.z, bv.z, fmaf(bv.w, bv.w, b2))));
        m2  = fmaf(mv.x, mv.x, fmaf(mv.y, mv.y, fmaf(mv.z, mv.z, fmaf(mv.w, mv.w, m2))));
        fin &= (fabsf(bv.x) <= 3.4028234e38f) & (fabsf(bv.y) <= 3.4028234e38f) &
               (fabsf(bv.z) <= 3.4028234e38f) & (fabsf(bv.w) <= 3.4028234e38f);
    }
    dot = wsum(dot); b2 = wsum(b2); m2 = wsum(m2);
    fin = __all_sync(0xffffffffu, fin);
    __shared__ float sd[4], sb[4], sm2[4];
    __shared__ int sf[4];
    if (lane == 0) { sd[w] = dot; sb[w] = b2; sm2[w] = m2; sf[w] = fin; }
    __syncthreads();
    if (t == 0) {
        float dt = sd[0] + sd[1] + sd[2] + sd[3];
        float bb = sb[0] + sb[1] + sb[2] + sb[3];
        float mm = sm2[0] + sm2[1] + sm2[2] + sm2[3];
        float bnorm = fmaxf(sqrtf(bb), 1e-12f);
        float mnorm = fmaxf(sqrtf(mm), 1e-12f);
        g_sims[n] = dt / (bnorm * mnorm);
        g_valid[n] = (sf[0] & sf[1] & sf[2] & sf[3]) && (sqrtf(bb) >= 1e-6f);
    }
    __shared__ int is_last;
    if (t == 0) {
        __threadfence();
        int c = atomicAdd(&g_ctr, 1);
        is_last = (c == gridDim.x - 1) ? 1 : 0;
    }
    __syncthreads();
    if (!is_last) return;

    float best = -3.0e38f; int bidx = 0x7fffffff;
    for (int i = t; i < N; i += 128) {
        float v = g_sims[i];
        if (v > best) { best = v; bidx = i; }
    }
#pragma unroll
    for (int o = 16; o > 0; o >>= 1) {
        float ov = __shfl_xor_sync(0xffffffffu, best, o);
        int   oi = __shfl_xor_sync(0xffffffffu, bidx, o);
        if (ov > best || (ov == best && oi < bidx)) { best = ov; bidx = oi; }
    }
    __shared__ float svv[4]; __shared__ int sii[4];
    if (lane == 0) { svv[w] = best; sii[w] = bidx; }
    __syncthreads();
    if (t == 0) {
        float bv = svv[0]; int bi = sii[0];
#pragma unroll
        for (int i = 1; i < 4; i++) {
            if (svv[i] > bv || (svv[i] == bv && sii[i] < bi)) { bv = svv[i]; bi = sii[i]; }
        }
        float sim_val = fminf(fmaxf(bv, 0.0f), 1.0f);
        float kb = fminf(fmaxf(expf(p_lkb[0]), 0.01f), 4.0f);
        float kd = fminf(fmaxf(expf(p_lkd[0]), 0.01f), 0.9f);
        float fl = facil[bi] * ((sim_val > 0.88f) ? 2.0f : 1.0f);
        float mod = (fl - 1.0f) * sim_val;
        float boost = 1.0f + kb * mod;
        float damp = fmaxf(0.01f, 1.0f - kd * mod);
        g_nidx = bi;
        if (g_valid[bi]) { g_damp = damp; g_qscale = (boost - damp) / damp; }
        else             { g_damp = 1.0f; g_qscale = 0.0f; }
        g_ctr = 0;
        g_ctr2 = 0;
    }
}

// ------- pass 2: warp-pair per row, register-pipelined x loads ----------
__global__ void __launch_bounds__(BLK, 4) k_pass2(
    const float* __restrict__ x, const float* __restrict__ buf,
    float* __restrict__ out, int M)
{
    __shared__ float4 s_v[D_ / 4];
    __shared__ float s_p[2][PAIRS][2];
    const int t = threadIdx.x;
    const int lane = t & 31, w = t >> 5;
    const int pair = w >> 1, half = w & 1;
    const float damp = g_damp;
    const float qscale = g_qscale;
    const int ni = g_nidx;

    {
        const float4* vp = (const float4*)(buf + (size_t)ni * D_);
        for (int i = t; i < D_ / 4; i += BLK) s_v[i] = vp[i];
    }
    __syncthreads();

    const int voff = half * 128 + lane;
    const int stride = GRID2 * PAIRS;

    // prologue
    int row = blockIdx.x * PAIRS + pair;
    float4 X[4];
    float ga0 = 0.f;
    if (row < M) {
        const float4* xp = (const float4*)(x + (size_t)row * D_) + voff;
#pragma unroll
        for (int k = 0; k < 4; k++) X[k] = __ldcs(xp + 32 * k);
        ga0 = g_gate[row];
    }
    int parity = 0;

    while (row < M) {
        // issue NEXT row's loads now
        const int rown = row + stride;
        float4 NX[4];
        float gan = 0.f;
        if (rown < M) {
            const float4* xq = (const float4*)(x + (size_t)rown * D_) + voff;
#pragma unroll
            for (int k = 0; k < 4; k++) NX[k] = __ldcs(xq + 32 * k);
            gan = g_gate[rown];
        }

        const float gad = 0.5f * damp * ga0;
        float4 Y[4];
        float proj = 0.f;
#pragma unroll
        for (int k = 0; k < 4; k++) {
            float4 Xk = X[k];
            float4 V = s_v[voff + 32 * k];
            float4 yy;
            float u0 = 0.7978845608028654f * fmaf(0.044715f * Xk.x, Xk.x * Xk.x, Xk.x);
            float u1 = 0.7978845608028654f * fmaf(0.044715f * Xk.y, Xk.y * Xk.y, Xk.y);
            float u2 = 0.7978845608028654f * fmaf(0.044715f * Xk.z, Xk.z * Xk.z, Xk.z);
            float u3 = 0.7978845608028654f * fmaf(0.044715f * Xk.w, Xk.w * Xk.w, Xk.w);
            yy.x = (Xk.x * gad) * (1.0f + tanh_ap(u0));
            yy.y = (Xk.y * gad) * (1.0f + tanh_ap(u1));
            yy.z = (Xk.z * gad) * (1.0f + tanh_ap(u2));
            yy.w = (Xk.w * gad) * (1.0f + tanh_ap(u3));
            Y[k] = yy;
            proj = fmaf(yy.x, V.x, fmaf(yy.y, V.y, fmaf(yy.z, V.z, fmaf(yy.w, V.w, proj))));
        }
        proj = wsum(proj);
        if (lane == 0) s_p[parity][pair][half] = proj;
        asm volatile("bar.sync %0, %1;" :: "r"(pair + 1), "r"(64) : "memory");
        const float q = (s_p[parity][pair][0] + s_p[parity][pair][1]) * qscale;
        float4* op = (float4*)(out + (size_t)row * D_) + voff;
#pragma unroll
        for (int k = 0; k < 4; k++) {
            float4 V = s_v[voff + 32 * k];
            float4 O;
            O.x = fmaf(q, V.x, Y[k].x);
            O.y = fmaf(q, V.y, Y[k].y);
            O.z = fmaf(q, V.z, Y[k].z);
            O.w = fmaf(q, V.w, Y[k].w);
            __stcs(op + 32 * k, O);
        }

        // rotate pipeline
        row = rown;
        ga0 = gan;
        parity ^= 1;
#pragma unroll
        for (int k = 0; k < 4; k++) X[k] = NX[k];
    }
}

extern "C" void kernel_launch(void* const* d_in, const int* in_sizes, int n_in,
                              void* d_out, int out_size)
{
    const float* x      = (const float*)d_in[0];
    const float* lt_in  = (const float*)d_in[1];
    const float* lt_out = (const float*)d_in[2];
    const float* la_in  = (const float*)d_in[3];
    const float* la_out = (const float*)d_in[4];
    const float* lkb    = (const float*)d_in[5];
    const float* lkd    = (const float*)d_in[6];
    const float* ema_x  = (const float*)d_in[7];
    const float* ema_x2 = (const float*)d_in[8];
    const float* ema_y  = (const float*)d_in[9];
    const float* ema_y2 = (const float*)d_in[10];
    const float* buf    = (const float*)d_in[11];
    const float* facil  = (const float*)d_in[12];

    const int M = in_sizes[0] / D_;   // 16384
    const int N = in_sizes[11] / D_;  // 512
    float* out = (float*)d_out;

    k_pass1<<<GRID1, BLK>>>(x, ema_x, ema_x2, ema_y, ema_y2,
                            lt_in, lt_out, la_in, la_out, M);
    k_mid<<<N, 128>>>(buf, facil, lkb, lkd, N, 1.0f / (float)M);
    k_pass2<<<GRID2, BLK>>>(x, buf, out, M);
}